// round 12
// baseline (speedup 1.0000x reference)
#include <cuda_runtime.h>
#include <cuda_fp16.h>
#include <cstdint>

// Problem constants (fixed by the dataset)
#define BATCH 2
#define CH    128
#define DW    64
#define DL    64
#define DH    64
#define SPAT  (DW*DL*DH)          // 262144
#define OUTW  7
#define OUTL  7
#define OUTH  7
#define NBINS (OUTW*OUTL*OUTH)    // 343

// Scratch: input transposed to (B, W, L, H, C) in fp16 so channels are
// contiguous. 2 * 262144 * 128 halves = 128 MB static device array.
__device__ __half g_vol[(size_t)BATCH * SPAT * CH];

struct alignas(16) H8 { __half2 a, b, c, d; };

// ---------------------------------------------------------------------------
// Kernel 1: transpose (B, C, S) fp32 -> (B, S, C) fp16, S = W*L*H.
// 128-spatial x 32-channel tile, 256 threads.
// Loads: 4x float4 per thread (512B contiguous runs per channel row).
// Stores: 2x 16B half8 per thread (64B contiguous per spatial row).
// ---------------------------------------------------------------------------
__global__ void __launch_bounds__(256)
transpose_half_kernel(const float* __restrict__ in)
{
    __shared__ float tile[128][33];

    const int b  = blockIdx.z;
    const int t  = threadIdx.x;
    const int s0 = blockIdx.x * 128;
    const int c0 = blockIdx.y * 32;

    // Phase 1: rows = channel (32), cols = spatial (128).
    {
        const int c_local = t >> 3;          // 0..31
        const int s4      = t & 7;           // 0..7
        const float* src = in + ((size_t)(b * CH + c0 + c_local)) * SPAT + s0;
        #pragma unroll
        for (int v = 0; v < 4; ++v) {
            const int s = (s4 + v * 8) * 4;  // 0..124 step 4
            const float4 q = *reinterpret_cast<const float4*>(src + s);
            // bank = (4*(t&7) + i + (t>>3)) % 32 : full permutation, conflict-free
            tile[s + 0][c_local] = q.x;
            tile[s + 1][c_local] = q.y;
            tile[s + 2][c_local] = q.z;
            tile[s + 3][c_local] = q.w;
        }
    }
    __syncthreads();
    // Phase 2: each thread packs 8 consecutive channels into one 16B store.
    {
        const int c8 = (t & 3) * 8;          // 0,8,16,24
        #pragma unroll
        for (int u = 0; u < 2; ++u) {
            const int s_local = (t >> 2) + u * 64;   // 0..127
            H8 h;
            h.a = __floats2half2_rn(tile[s_local][c8 + 0], tile[s_local][c8 + 1]);
            h.b = __floats2half2_rn(tile[s_local][c8 + 2], tile[s_local][c8 + 3]);
            h.c = __floats2half2_rn(tile[s_local][c8 + 4], tile[s_local][c8 + 5]);
            h.d = __floats2half2_rn(tile[s_local][c8 + 6], tile[s_local][c8 + 7]);
            *reinterpret_cast<H8*>(
                g_vol + ((size_t)b * SPAT + s0 + s_local) * CH + c0 + c8) = h;
        }
    }
}

// ---------------------------------------------------------------------------
// Kernel 2: ROI-align rotated 3D gather from the fp16 channel-contiguous
// volume. One warp per (roi, bin); lane owns 4 channels (one uint2 / 8B).
// Per-sample accumulation in half2 (HFMA2), widened to fp32 per sample.
// Output staged through smem so global writes are bin-contiguous.
// ---------------------------------------------------------------------------
__global__ void __launch_bounds__(256)
roi_gather_kernel(const float* __restrict__ rois,
                  const float* __restrict__ scale_p,
                  float* __restrict__ out,
                  int N)
{
    // 8 bins x 128 channels staging. float4 rows padded to 33 -> scalar reads
    // at pitch 132 floats are bank-conflict-free.
    __shared__ float4 s_out4[8][33];

    const int warp = threadIdx.x >> 5;
    const int lane = threadIdx.x & 31;
    const int bin  = blockIdx.x * 8 + warp;
    const int n    = blockIdx.y;

    float4 acc = make_float4(0.f, 0.f, 0.f, 0.f);

    if (bin < NBINS) {
        const float scale = *scale_p;
        const float* r = rois + (size_t)n * 8;
        const int   b  = (int)r[0];
        const float cx = r[1] * scale;
        const float cy = r[2] * scale;
        const float cz = r[3] * scale;
        const float sx = r[4] * scale;
        const float sy = r[5] * scale;
        const float sz = r[6] * scale;
        const float th = r[7];
        const float ct = cosf(th);
        const float st = sinf(th);

        // step = (size/nbins)/SR, matching reference arithmetic order
        const float stepx = (sx / 7.0f) * 0.5f;
        const float stepy = (sy / 7.0f) * 0.5f;
        const float stepz = (sz / 7.0f) * 0.5f;

        const int ow  = bin / 49;
        const int rem = bin % 49;
        const int ol  = rem / 7;
        const int oh  = rem % 7;

        // byte-addressed base for this lane's 4-channel slice (8B per voxel,
        // 256B per spatial step). All corner offsets fit in 32-bit ints.
        const char* __restrict__ vbase =
            reinterpret_cast<const char*>(g_vol) + (size_t)b * SPAT * 256 + lane * 8;

        #pragma unroll
        for (int jx = 0; jx < 2; ++jx) {
            const int ix = ow * 2 + jx;
            const float fx = -sx * 0.5f + ((float)ix + 0.5f) * stepx;
            #pragma unroll
            for (int jy = 0; jy < 2; ++jy) {
                const int iy = ol * 2 + jy;
                const float fy = -sy * 0.5f + ((float)iy + 0.5f) * stepy;
                const float xs = ct * fx - st * fy + cx;
                const float ys = st * fx + ct * fy + cy;

                const bool vxy = (xs > -1.0f) && (xs < (float)DW) &&
                                 (ys > -1.0f) && (ys < (float)DL);
                if (!vxy) continue;

                const float xc = fminf(fmaxf(xs, 0.f), (float)(DW - 1));
                const float yc = fminf(fmaxf(ys, 0.f), (float)(DL - 1));
                const int x0 = (int)floorf(xc);
                const int y0 = (int)floorf(yc);
                const float lx = xc - (float)x0, hx = 1.f - lx;
                const float ly = yc - (float)y0, hy = 1.f - ly;

                const int ox = (x0 + 1 <= DW - 1) ? (DL * DH * 256) : 0;
                const int oy = (y0 + 1 <= DL - 1) ? (DH * 256)      : 0;
                const int oxybase = ((x0 * DL + y0) * DH) * 256;

                // xy weight products, shared by both z samples
                const float wxy00 = hx * hy;
                const float wxy01 = hx * ly;
                const float wxy10 = lx * hy;
                const float wxy11 = lx * ly;

                #pragma unroll
                for (int jz = 0; jz < 2; ++jz) {
                    const int iz = oh * 2 + jz;
                    const float zs = (-sz * 0.5f + ((float)iz + 0.5f) * stepz) + cz;
                    if (!((zs > -1.0f) && (zs < (float)DH))) continue;

                    const float zc = fminf(fmaxf(zs, 0.f), (float)(DH - 1));
                    const int z0 = (int)floorf(zc);
                    const float lz = zc - (float)z0, hz = 1.f - lz;
                    const int oz = (z0 + 1 <= DH - 1) ? 256 : 0;

                    const int o000 = oxybase + z0 * 256;

                    const uint2 v000 = *reinterpret_cast<const uint2*>(vbase + o000);
                    const uint2 v001 = *reinterpret_cast<const uint2*>(vbase + o000 + oz);
                    const uint2 v010 = *reinterpret_cast<const uint2*>(vbase + o000 + oy);
                    const uint2 v011 = *reinterpret_cast<const uint2*>(vbase + o000 + oy + oz);
                    const uint2 v100 = *reinterpret_cast<const uint2*>(vbase + o000 + ox);
                    const uint2 v101 = *reinterpret_cast<const uint2*>(vbase + o000 + ox + oz);
                    const uint2 v110 = *reinterpret_cast<const uint2*>(vbase + o000 + ox + oy);
                    const uint2 v111 = *reinterpret_cast<const uint2*>(vbase + o000 + ox + oy + oz);

                    const __half2 w000 = __float2half2_rn(wxy00 * hz);
                    const __half2 w001 = __float2half2_rn(wxy00 * lz);
                    const __half2 w010 = __float2half2_rn(wxy01 * hz);
                    const __half2 w011 = __float2half2_rn(wxy01 * lz);
                    const __half2 w100 = __float2half2_rn(wxy10 * hz);
                    const __half2 w101 = __float2half2_rn(wxy10 * lz);
                    const __half2 w110 = __float2half2_rn(wxy11 * hz);
                    const __half2 w111 = __float2half2_rn(wxy11 * lz);

                    // per-sample fp16 accumulation (8 convex-weighted terms)
                    __half2 a0 = __hmul2(*reinterpret_cast<const __half2*>(&v000.x), w000);
                    __half2 a1 = __hmul2(*reinterpret_cast<const __half2*>(&v000.y), w000);
                    a0 = __hfma2(*reinterpret_cast<const __half2*>(&v001.x), w001, a0);
                    a1 = __hfma2(*reinterpret_cast<const __half2*>(&v001.y), w001, a1);
                    a0 = __hfma2(*reinterpret_cast<const __half2*>(&v010.x), w010, a0);
                    a1 = __hfma2(*reinterpret_cast<const __half2*>(&v010.y), w010, a1);
                    a0 = __hfma2(*reinterpret_cast<const __half2*>(&v011.x), w011, a0);
                    a1 = __hfma2(*reinterpret_cast<const __half2*>(&v011.y), w011, a1);
                    a0 = __hfma2(*reinterpret_cast<const __half2*>(&v100.x), w100, a0);
                    a1 = __hfma2(*reinterpret_cast<const __half2*>(&v100.y), w100, a1);
                    a0 = __hfma2(*reinterpret_cast<const __half2*>(&v101.x), w101, a0);
                    a1 = __hfma2(*reinterpret_cast<const __half2*>(&v101.y), w101, a1);
                    a0 = __hfma2(*reinterpret_cast<const __half2*>(&v110.x), w110, a0);
                    a1 = __hfma2(*reinterpret_cast<const __half2*>(&v110.y), w110, a1);
                    a0 = __hfma2(*reinterpret_cast<const __half2*>(&v111.x), w111, a0);
                    a1 = __hfma2(*reinterpret_cast<const __half2*>(&v111.y), w111, a1);

                    // widen once per sample into fp32 accumulator
                    const float2 f0 = __half22float2(a0);
                    const float2 f1 = __half22float2(a1);
                    acc.x += f0.x; acc.y += f0.y;
                    acc.z += f1.x; acc.w += f1.y;
                }
            }
        }
        acc.x *= 0.125f; acc.y *= 0.125f; acc.z *= 0.125f; acc.w *= 0.125f;
    }

    // Stage: warp=bin row, lane=4-channel float4. STS.128, warp-contiguous.
    s_out4[warp][lane] = acc;
    __syncthreads();

    // Write: bins contiguous in gmem (out[n][c][bin]). Each group of 8 lanes
    // writes 8 consecutive bins for one channel -> full 32B sectors.
    {
        const float* s_outf = reinterpret_cast<const float*>(s_out4);
        const int bin_local = threadIdx.x & 7;
        const int bin_g     = blockIdx.x * 8 + bin_local;
        if (bin_g < NBINS) {
            const int cbase = threadIdx.x >> 3;   // 0..31
            #pragma unroll
            for (int k = 0; k < 4; ++k) {
                const int c = cbase + 32 * k;
                out[((size_t)n * CH + c) * NBINS + bin_g] =
                    s_outf[bin_local * 132 + c];
            }
        }
    }
}

extern "C" void kernel_launch(void* const* d_in, const int* in_sizes, int n_in,
                              void* d_out, int out_size)
{
    const float* input  = (const float*)d_in[0];
    const float* rois   = (const float*)d_in[1];
    const float* scale  = (const float*)d_in[2];
    float* out = (float*)d_out;
    const int N = in_sizes[1] / 8;

    {
        dim3 grid(SPAT / 128, CH / 32, BATCH);   // (2048, 4, 2)
        transpose_half_kernel<<<grid, 256>>>(input);
    }
    {
        dim3 grid((NBINS + 7) / 8, N);           // (43, 128)
        roi_gather_kernel<<<grid, 256>>>(rois, scale, out, N);
    }
}

// round 14
// speedup vs baseline: 1.2101x; 1.2101x over previous
#include <cuda_runtime.h>
#include <cuda_fp16.h>
#include <cstdint>

// Problem constants (fixed by the dataset)
#define BATCH 2
#define CH    128
#define DW    64
#define DL    64
#define DH    64
#define SPAT  (DW*DL*DH)          // 262144
#define OUTW  7
#define OUTL  7
#define OUTH  7
#define NBINS (OUTW*OUTL*OUTH)    // 343

// Scratch: input transposed to (B, W, L, H, C) in fp16 so channels are
// contiguous. 2 * 262144 * 128 halves = 128 MB static device array.
__device__ __half g_vol[(size_t)BATCH * SPAT * CH];

struct alignas(8) H4 { __half2 a, b; };

// ---------------------------------------------------------------------------
// Kernel 1: transpose (B, C, S) fp32 -> (B, S, C) fp16, S = W*L*H.
// 32x32 tile, 256 threads. float4 global loads, 8-byte half4 global stores.
// (R10 version — best measured.)
// ---------------------------------------------------------------------------
__global__ void __launch_bounds__(256)
transpose_half_kernel(const float* __restrict__ in)
{
    __shared__ float tile[32][33];

    const int b  = blockIdx.z;
    const int t  = threadIdx.x;
    const int s0 = blockIdx.x * 32;
    const int c0 = blockIdx.y * 32;

    // Phase 1: load float4 along spatial (contiguous). rows=channel.
    {
        const int c_local = t >> 3;          // 0..31
        const int s4      = t & 7;           // 0..7  (x4 spatial)
        const float4 v = *reinterpret_cast<const float4*>(
            in + ((size_t)(b * CH + c0 + c_local)) * SPAT + s0 + s4 * 4);
        tile[s4 * 4 + 0][c_local] = v.x;     // banks conflict-free
        tile[s4 * 4 + 1][c_local] = v.y;
        tile[s4 * 4 + 2][c_local] = v.z;
        tile[s4 * 4 + 3][c_local] = v.w;
    }
    __syncthreads();
    // Phase 2: write 4 consecutive channels as one 8-byte half4 store.
    {
        const int s_local = t >> 3;          // 0..31
        const int c4      = t & 7;           // 0..7  (x4 channels)
        H4 h;
        h.a = __floats2half2_rn(tile[s_local][c4 * 4 + 0], tile[s_local][c4 * 4 + 1]);
        h.b = __floats2half2_rn(tile[s_local][c4 * 4 + 2], tile[s_local][c4 * 4 + 3]);
        *reinterpret_cast<H4*>(
            g_vol + ((size_t)b * SPAT + s0 + s_local) * CH + c0 + c4 * 4) = h;
    }
}

// ---------------------------------------------------------------------------
// Kernel 2: ROI-align rotated 3D gather.
// One warp per (roi, bin). Half-warps split the jz sample dimension;
// within a half-warp, lane owns 8 channels (one uint4 / 16B).
// fp32 accumulation (8 independent chains). Cross-half shfl reduce at end.
// ---------------------------------------------------------------------------
__device__ __forceinline__ void acc_corner(float* a, const uint4& v, float w)
{
    const float2 p0 = __half22float2(*reinterpret_cast<const __half2*>(&v.x));
    const float2 p1 = __half22float2(*reinterpret_cast<const __half2*>(&v.y));
    const float2 p2 = __half22float2(*reinterpret_cast<const __half2*>(&v.z));
    const float2 p3 = __half22float2(*reinterpret_cast<const __half2*>(&v.w));
    a[0] += w * p0.x; a[1] += w * p0.y;
    a[2] += w * p1.x; a[3] += w * p1.y;
    a[4] += w * p2.x; a[5] += w * p2.y;
    a[6] += w * p3.x; a[7] += w * p3.y;
}

__global__ void __launch_bounds__(256)
roi_gather_kernel(const float* __restrict__ rois,
                  const float* __restrict__ scale_p,
                  float* __restrict__ out,
                  int N)
{
    // 8 bins x 128 channels staging. float4 rows padded to 33 -> scalar reads
    // at pitch 132 floats are bank-conflict-free.
    __shared__ float4 s_out4[8][33];

    const int warp   = threadIdx.x >> 5;
    const int lane   = threadIdx.x & 31;
    const int zhalf  = lane >> 4;        // which jz sample this half-warp does
    const int laneIn = lane & 15;        // 8-channel group within half-warp
    const int bin    = blockIdx.x * 8 + warp;
    const int n      = blockIdx.y;

    float a[8] = {0.f, 0.f, 0.f, 0.f, 0.f, 0.f, 0.f, 0.f};

    if (bin < NBINS) {
        const float scale = *scale_p;
        const float* r = rois + (size_t)n * 8;
        const int   b  = (int)r[0];
        const float cx = r[1] * scale;
        const float cy = r[2] * scale;
        const float cz = r[3] * scale;
        const float sx = r[4] * scale;
        const float sy = r[5] * scale;
        const float sz = r[6] * scale;
        const float th = r[7];
        const float ct = cosf(th);
        const float st = sinf(th);

        // step = (size/nbins)/SR, matching reference arithmetic order
        const float stepx = (sx / 7.0f) * 0.5f;
        const float stepy = (sy / 7.0f) * 0.5f;
        const float stepz = (sz / 7.0f) * 0.5f;

        const int ow  = bin / 49;
        const int rem = bin % 49;
        const int ol  = rem / 7;
        const int oh  = rem % 7;

        // ---- z: loop-invariant for this lane (depends only on bin + zhalf)
        const int   iz = oh * 2 + zhalf;
        const float zs = (-sz * 0.5f + ((float)iz + 0.5f) * stepz) + cz;
        const float zval = ((zs > -1.0f) && (zs < (float)DH)) ? 1.0f : 0.0f;
        const float zc = fminf(fmaxf(zs, 0.f), (float)(DH - 1));
        const int   z0 = (int)floorf(zc);
        const float lz = zc - (float)z0;
        const float wz0 = (1.0f - lz) * zval;     // weight for z0 plane
        const float wz1 = lz * zval;              // weight for z1 plane
        const int   oz  = (z0 + 1 <= DH - 1) ? 256 : 0;

        // byte-addressed base for this lane's 8-channel slice (16B per voxel,
        // 256B per spatial step). All corner offsets fit in 32-bit ints.
        const char* __restrict__ vbase =
            reinterpret_cast<const char*>(g_vol) + (size_t)b * SPAT * 256 + laneIn * 16;

        #pragma unroll
        for (int jx = 0; jx < 2; ++jx) {
            const int ix = ow * 2 + jx;
            const float fx = -sx * 0.5f + ((float)ix + 0.5f) * stepx;
            #pragma unroll
            for (int jy = 0; jy < 2; ++jy) {
                const int iy = ol * 2 + jy;
                const float fy = -sy * 0.5f + ((float)iy + 0.5f) * stepy;
                const float xs = ct * fx - st * fy + cx;
                const float ys = st * fx + ct * fy + cy;

                const bool vxy = (xs > -1.0f) && (xs < (float)DW) &&
                                 (ys > -1.0f) && (ys < (float)DL);
                if (!vxy) continue;

                const float xc = fminf(fmaxf(xs, 0.f), (float)(DW - 1));
                const float yc = fminf(fmaxf(ys, 0.f), (float)(DL - 1));
                const int x0 = (int)floorf(xc);
                const int y0 = (int)floorf(yc);
                const float lx = xc - (float)x0, hx = 1.f - lx;
                const float ly = yc - (float)y0, hy = 1.f - ly;

                const int ox = (x0 + 1 <= DW - 1) ? (DL * DH * 256) : 0;
                const int oy = (y0 + 1 <= DL - 1) ? (DH * 256)      : 0;
                const int o000 = ((x0 * DL + y0) * DH + z0) * 256;

                // 8 corner loads (2x2 xy corners x 2 z planes), batched for MLP
                const uint4 v00a = *reinterpret_cast<const uint4*>(vbase + o000);
                const uint4 v00b = *reinterpret_cast<const uint4*>(vbase + o000 + oz);
                const uint4 v01a = *reinterpret_cast<const uint4*>(vbase + o000 + oy);
                const uint4 v01b = *reinterpret_cast<const uint4*>(vbase + o000 + oy + oz);
                const uint4 v10a = *reinterpret_cast<const uint4*>(vbase + o000 + ox);
                const uint4 v10b = *reinterpret_cast<const uint4*>(vbase + o000 + ox + oz);
                const uint4 v11a = *reinterpret_cast<const uint4*>(vbase + o000 + ox + oy);
                const uint4 v11b = *reinterpret_cast<const uint4*>(vbase + o000 + ox + oy + oz);

                const float wxy00 = hx * hy;
                const float wxy01 = hx * ly;
                const float wxy10 = lx * hy;
                const float wxy11 = lx * ly;

                acc_corner(a, v00a, wxy00 * wz0);
                acc_corner(a, v00b, wxy00 * wz1);
                acc_corner(a, v01a, wxy01 * wz0);
                acc_corner(a, v01b, wxy01 * wz1);
                acc_corner(a, v10a, wxy10 * wz0);
                acc_corner(a, v10b, wxy10 * wz1);
                acc_corner(a, v11a, wxy11 * wz0);
                acc_corner(a, v11b, wxy11 * wz1);
            }
        }
    }

    // Combine the two jz halves: lane L and L+16 hold the same channels.
    #pragma unroll
    for (int k = 0; k < 8; ++k) {
        a[k] += __shfl_xor_sync(0xffffffffu, a[k], 16);
        a[k] *= 0.125f;
    }

    // Stage: lanes 0..15 write 8 channels = 2 float4 (STS.128).
    if (zhalf == 0) {
        s_out4[warp][laneIn * 2 + 0] = make_float4(a[0], a[1], a[2], a[3]);
        s_out4[warp][laneIn * 2 + 1] = make_float4(a[4], a[5], a[6], a[7]);
    }
    __syncthreads();

    // Write: bins contiguous in gmem (out[n][c][bin]). Each group of 8 lanes
    // writes 8 consecutive bins for one channel -> full 32B sectors.
    {
        const float* s_outf = reinterpret_cast<const float*>(s_out4);
        const int bin_local = threadIdx.x & 7;
        const int bin_g     = blockIdx.x * 8 + bin_local;
        if (bin_g < NBINS) {
            const int cbase = threadIdx.x >> 3;   // 0..31
            #pragma unroll
            for (int k = 0; k < 4; ++k) {
                const int c = cbase + 32 * k;
                out[((size_t)n * CH + c) * NBINS + bin_g] =
                    s_outf[bin_local * 132 + c];
            }
        }
    }
}

extern "C" void kernel_launch(void* const* d_in, const int* in_sizes, int n_in,
                              void* d_out, int out_size)
{
    const float* input  = (const float*)d_in[0];
    const float* rois   = (const float*)d_in[1];
    const float* scale  = (const float*)d_in[2];
    float* out = (float*)d_out;
    const int N = in_sizes[1] / 8;

    {
        dim3 grid(SPAT / 32, CH / 32, BATCH);   // (8192, 4, 2)
        transpose_half_kernel<<<grid, 256>>>(input);
    }
    {
        dim3 grid((NBINS + 7) / 8, N);          // (43, 128)
        roi_gather_kernel<<<grid, 256>>>(rois, scale, out, N);
    }
}

// round 15
// speedup vs baseline: 1.2208x; 1.0088x over previous
#include <cuda_runtime.h>
#include <cuda_fp16.h>
#include <cstdint>

// Problem constants (fixed by the dataset)
#define BATCH 2
#define CH    128
#define DW    64
#define DL    64
#define DH    64
#define SPAT  (DW*DL*DH)          // 262144
#define OUTW  7
#define OUTL  7
#define OUTH  7
#define NBINS (OUTW*OUTL*OUTH)    // 343

// Scratch: input transposed to (B, W, L, H, C) in fp16 so channels are
// contiguous. 2 * 262144 * 128 halves = 128 MB static device array.
__device__ __half g_vol[(size_t)BATCH * SPAT * CH];

struct alignas(16) H8 { __half2 a, b, c, d; };

// ---------------------------------------------------------------------------
// Kernel 1: transpose (B, C, S) fp32 -> (B, S, C) fp16, S = W*L*H.
// 128-spatial x 32-channel tile, 256 threads, 16384 blocks.
// Loads: 4x float4 per thread (512B contiguous runs per channel row).
// Stores: 2x 16B half8 per thread (64B contiguous per spatial row).
// ---------------------------------------------------------------------------
__global__ void __launch_bounds__(256)
transpose_half_kernel(const float* __restrict__ in)
{
    __shared__ float tile[128][33];

    const int b  = blockIdx.z;
    const int t  = threadIdx.x;
    const int s0 = blockIdx.x * 128;
    const int c0 = blockIdx.y * 32;

    // Phase 1: rows = channel (32), cols = spatial (128).
    {
        const int c_local = t >> 3;          // 0..31
        const int s4      = t & 7;           // 0..7
        const float* src = in + ((size_t)(b * CH + c0 + c_local)) * SPAT + s0;
        #pragma unroll
        for (int v = 0; v < 4; ++v) {
            const int s = (s4 + v * 8) * 4;  // 0..124 step 4
            const float4 q = *reinterpret_cast<const float4*>(src + s);
            // bank = (4*(t&7)+i + (t>>3)) % 32 : full permutation, conflict-free
            tile[s + 0][c_local] = q.x;
            tile[s + 1][c_local] = q.y;
            tile[s + 2][c_local] = q.z;
            tile[s + 3][c_local] = q.w;
        }
    }
    __syncthreads();
    // Phase 2: each thread packs 8 consecutive channels into one 16B store.
    {
        const int c8 = (t & 3) * 8;          // 0,8,16,24
        #pragma unroll
        for (int u = 0; u < 2; ++u) {
            const int s_local = (t >> 2) + u * 64;   // 0..127
            H8 h;
            h.a = __floats2half2_rn(tile[s_local][c8 + 0], tile[s_local][c8 + 1]);
            h.b = __floats2half2_rn(tile[s_local][c8 + 2], tile[s_local][c8 + 3]);
            h.c = __floats2half2_rn(tile[s_local][c8 + 4], tile[s_local][c8 + 5]);
            h.d = __floats2half2_rn(tile[s_local][c8 + 6], tile[s_local][c8 + 7]);
            *reinterpret_cast<H8*>(
                g_vol + ((size_t)b * SPAT + s0 + s_local) * CH + c0 + c8) = h;
        }
    }
}

// ---------------------------------------------------------------------------
// Kernel 2: ROI-align rotated 3D gather.
// One warp per (roi, bin). Half-warps split the jz sample dimension;
// within a half-warp, lane owns 8 channels (one uint4 / 16B).
// Per-(jx,jy): 8 corner loads; per half2 slot an 8-product fp16 TREE
// (8 HMUL2 independent, depth-3 HADD2 tree), widened to fp32 per iteration.
// Cross-half shfl reduce at end.
// ---------------------------------------------------------------------------
__device__ __forceinline__ __half2 h2(const unsigned int& u)
{
    return *reinterpret_cast<const __half2*>(&u);
}

__global__ void __launch_bounds__(256)
roi_gather_kernel(const float* __restrict__ rois,
                  const float* __restrict__ scale_p,
                  float* __restrict__ out,
                  int N)
{
    // 8 bins x 128 channels staging. float4 rows padded to 33 -> scalar reads
    // at pitch 132 floats are bank-conflict-free.
    __shared__ float4 s_out4[8][33];

    const int warp   = threadIdx.x >> 5;
    const int lane   = threadIdx.x & 31;
    const int zhalf  = lane >> 4;        // which jz sample this half-warp does
    const int laneIn = lane & 15;        // 8-channel group within half-warp
    const int bin    = blockIdx.x * 8 + warp;
    const int n      = blockIdx.y;

    float a[8] = {0.f, 0.f, 0.f, 0.f, 0.f, 0.f, 0.f, 0.f};

    if (bin < NBINS) {
        const float scale = *scale_p;
        const float* r = rois + (size_t)n * 8;
        const int   b  = (int)r[0];
        const float cx = r[1] * scale;
        const float cy = r[2] * scale;
        const float cz = r[3] * scale;
        const float sx = r[4] * scale;
        const float sy = r[5] * scale;
        const float sz = r[6] * scale;
        const float th = r[7];
        const float ct = cosf(th);
        const float st = sinf(th);

        // step = (size/nbins)/SR, matching reference arithmetic order
        const float stepx = (sx / 7.0f) * 0.5f;
        const float stepy = (sy / 7.0f) * 0.5f;
        const float stepz = (sz / 7.0f) * 0.5f;

        const int ow  = bin / 49;
        const int rem = bin % 49;
        const int ol  = rem / 7;
        const int oh  = rem % 7;

        // ---- z: loop-invariant for this lane (depends only on bin + zhalf)
        const int   iz = oh * 2 + zhalf;
        const float zs = (-sz * 0.5f + ((float)iz + 0.5f) * stepz) + cz;
        const float zval = ((zs > -1.0f) && (zs < (float)DH)) ? 1.0f : 0.0f;
        const float zc = fminf(fmaxf(zs, 0.f), (float)(DH - 1));
        const int   z0 = (int)floorf(zc);
        const float lz = zc - (float)z0;
        const float wz0 = (1.0f - lz) * zval;     // weight for z0 plane
        const float wz1 = lz * zval;              // weight for z1 plane
        const int   oz  = (z0 + 1 <= DH - 1) ? 256 : 0;

        // byte-addressed base for this lane's 8-channel slice (16B per voxel,
        // 256B per spatial step). All corner offsets fit in 32-bit ints.
        const char* __restrict__ vbase =
            reinterpret_cast<const char*>(g_vol) + (size_t)b * SPAT * 256 + laneIn * 16;

        #pragma unroll
        for (int jx = 0; jx < 2; ++jx) {
            const int ix = ow * 2 + jx;
            const float fx = -sx * 0.5f + ((float)ix + 0.5f) * stepx;
            #pragma unroll
            for (int jy = 0; jy < 2; ++jy) {
                const int iy = ol * 2 + jy;
                const float fy = -sy * 0.5f + ((float)iy + 0.5f) * stepy;
                const float xs = ct * fx - st * fy + cx;
                const float ys = st * fx + ct * fy + cy;

                const bool vxy = (xs > -1.0f) && (xs < (float)DW) &&
                                 (ys > -1.0f) && (ys < (float)DL);
                if (!vxy) continue;

                const float xc = fminf(fmaxf(xs, 0.f), (float)(DW - 1));
                const float yc = fminf(fmaxf(ys, 0.f), (float)(DL - 1));
                const int x0 = (int)floorf(xc);
                const int y0 = (int)floorf(yc);
                const float lx = xc - (float)x0, hx = 1.f - lx;
                const float ly = yc - (float)y0, hy = 1.f - ly;

                const int ox = (x0 + 1 <= DW - 1) ? (DL * DH * 256) : 0;
                const int oy = (y0 + 1 <= DL - 1) ? (DH * 256)      : 0;
                const int o000 = ((x0 * DL + y0) * DH + z0) * 256;

                // 8 corner loads (2x2 xy corners x 2 z planes), batched for MLP
                const uint4 v00a = *reinterpret_cast<const uint4*>(vbase + o000);
                const uint4 v00b = *reinterpret_cast<const uint4*>(vbase + o000 + oz);
                const uint4 v01a = *reinterpret_cast<const uint4*>(vbase + o000 + oy);
                const uint4 v01b = *reinterpret_cast<const uint4*>(vbase + o000 + oy + oz);
                const uint4 v10a = *reinterpret_cast<const uint4*>(vbase + o000 + ox);
                const uint4 v10b = *reinterpret_cast<const uint4*>(vbase + o000 + ox + oz);
                const uint4 v11a = *reinterpret_cast<const uint4*>(vbase + o000 + ox + oy);
                const uint4 v11b = *reinterpret_cast<const uint4*>(vbase + o000 + ox + oy + oz);

                const float wxy00 = hx * hy;
                const float wxy01 = hx * ly;
                const float wxy10 = lx * hy;
                const float wxy11 = lx * ly;

                // fp16 duplicated weights (one F2FP each)
                const __half2 w00a = __float2half2_rn(wxy00 * wz0);
                const __half2 w00b = __float2half2_rn(wxy00 * wz1);
                const __half2 w01a = __float2half2_rn(wxy01 * wz0);
                const __half2 w01b = __float2half2_rn(wxy01 * wz1);
                const __half2 w10a = __float2half2_rn(wxy10 * wz0);
                const __half2 w10b = __float2half2_rn(wxy10 * wz1);
                const __half2 w11a = __float2half2_rn(wxy11 * wz0);
                const __half2 w11b = __float2half2_rn(wxy11 * wz1);

                const unsigned int* q00a = reinterpret_cast<const unsigned int*>(&v00a);
                const unsigned int* q00b = reinterpret_cast<const unsigned int*>(&v00b);
                const unsigned int* q01a = reinterpret_cast<const unsigned int*>(&v01a);
                const unsigned int* q01b = reinterpret_cast<const unsigned int*>(&v01b);
                const unsigned int* q10a = reinterpret_cast<const unsigned int*>(&v10a);
                const unsigned int* q10b = reinterpret_cast<const unsigned int*>(&v10b);
                const unsigned int* q11a = reinterpret_cast<const unsigned int*>(&v11a);
                const unsigned int* q11b = reinterpret_cast<const unsigned int*>(&v11b);

                #pragma unroll
                for (int k = 0; k < 4; ++k) {
                    // 8 independent products
                    const __half2 p0 = __hmul2(h2(q00a[k]), w00a);
                    const __half2 p1 = __hmul2(h2(q00b[k]), w00b);
                    const __half2 p2 = __hmul2(h2(q01a[k]), w01a);
                    const __half2 p3 = __hmul2(h2(q01b[k]), w01b);
                    const __half2 p4 = __hmul2(h2(q10a[k]), w10a);
                    const __half2 p5 = __hmul2(h2(q10b[k]), w10b);
                    const __half2 p6 = __hmul2(h2(q11a[k]), w11a);
                    const __half2 p7 = __hmul2(h2(q11b[k]), w11b);
                    // depth-3 pairwise tree
                    const __half2 s0 = __hadd2(p0, p1);
                    const __half2 s1 = __hadd2(p2, p3);
                    const __half2 s2 = __hadd2(p4, p5);
                    const __half2 s3 = __hadd2(p6, p7);
                    const __half2 t0 = __hadd2(s0, s1);
                    const __half2 t1 = __hadd2(s2, s3);
                    const __half2 sum = __hadd2(t0, t1);
                    // widen once per slot per iteration
                    const float2 f = __half22float2(sum);
                    a[k * 2 + 0] += f.x;
                    a[k * 2 + 1] += f.y;
                }
            }
        }
    }

    // Combine the two jz halves: lane L and L+16 hold the same channels.
    #pragma unroll
    for (int k = 0; k < 8; ++k) {
        a[k] += __shfl_xor_sync(0xffffffffu, a[k], 16);
        a[k] *= 0.125f;
    }

    // Stage: lanes 0..15 write 8 channels = 2 float4 (STS.128).
    if (zhalf == 0) {
        s_out4[warp][laneIn * 2 + 0] = make_float4(a[0], a[1], a[2], a[3]);
        s_out4[warp][laneIn * 2 + 1] = make_float4(a[4], a[5], a[6], a[7]);
    }
    __syncthreads();

    // Write: bins contiguous in gmem (out[n][c][bin]). Each group of 8 lanes
    // writes 8 consecutive bins for one channel -> full 32B sectors.
    {
        const float* s_outf = reinterpret_cast<const float*>(s_out4);
        const int bin_local = threadIdx.x & 7;
        const int bin_g     = blockIdx.x * 8 + bin_local;
        if (bin_g < NBINS) {
            const int cbase = threadIdx.x >> 3;   // 0..31
            #pragma unroll
            for (int k = 0; k < 4; ++k) {
                const int c = cbase + 32 * k;
                out[((size_t)n * CH + c) * NBINS + bin_g] =
                    s_outf[bin_local * 132 + c];
            }
        }
    }
}

extern "C" void kernel_launch(void* const* d_in, const int* in_sizes, int n_in,
                              void* d_out, int out_size)
{
    const float* input  = (const float*)d_in[0];
    const float* rois   = (const float*)d_in[1];
    const float* scale  = (const float*)d_in[2];
    float* out = (float*)d_out;
    const int N = in_sizes[1] / 8;

    {
        dim3 grid(SPAT / 128, CH / 32, BATCH);   // (2048, 4, 2)
        transpose_half_kernel<<<grid, 256>>>(input);
    }
    {
        dim3 grid((NBINS + 7) / 8, N);           // (43, 128)
        roi_gather_kernel<<<grid, 256>>>(rois, scale, out, N);
    }
}

// round 16
// speedup vs baseline: 1.2802x; 1.0486x over previous
#include <cuda_runtime.h>
#include <cuda_fp16.h>
#include <cstdint>

// Problem constants (fixed by the dataset)
#define BATCH 2
#define CH    128
#define DW    64
#define DL    64
#define DH    64
#define SPAT  (DW*DL*DH)          // 262144
#define OUTW  7
#define OUTL  7
#define OUTH  7
#define NBINS (OUTW*OUTL*OUTH)    // 343

// Scratch: input transposed to (B, W, L, H, C) in fp16 so channels are
// contiguous. 2 * 262144 * 128 halves = 128 MB static device array.
__device__ __half g_vol[(size_t)BATCH * SPAT * CH];

struct alignas(8) H4 { __half2 a, b; };

// ---------------------------------------------------------------------------
// Kernel 1: transpose (B, C, S) fp32 -> (B, S, C) fp16, S = W*L*H.
// 32x32 tile, 256 threads. float4 global loads, 8-byte half4 global stores.
// (R10/R14 version — best measured; 128-wide variant measured slower twice.)
// ---------------------------------------------------------------------------
__global__ void __launch_bounds__(256)
transpose_half_kernel(const float* __restrict__ in)
{
    __shared__ float tile[32][33];

    const int b  = blockIdx.z;
    const int t  = threadIdx.x;
    const int s0 = blockIdx.x * 32;
    const int c0 = blockIdx.y * 32;

    // Phase 1: load float4 along spatial (contiguous). rows=channel.
    {
        const int c_local = t >> 3;          // 0..31
        const int s4      = t & 7;           // 0..7  (x4 spatial)
        const float4 v = *reinterpret_cast<const float4*>(
            in + ((size_t)(b * CH + c0 + c_local)) * SPAT + s0 + s4 * 4);
        tile[s4 * 4 + 0][c_local] = v.x;     // banks conflict-free
        tile[s4 * 4 + 1][c_local] = v.y;
        tile[s4 * 4 + 2][c_local] = v.z;
        tile[s4 * 4 + 3][c_local] = v.w;
    }
    __syncthreads();
    // Phase 2: write 4 consecutive channels as one 8-byte half4 store.
    {
        const int s_local = t >> 3;          // 0..31
        const int c4      = t & 7;           // 0..7  (x4 channels)
        H4 h;
        h.a = __floats2half2_rn(tile[s_local][c4 * 4 + 0], tile[s_local][c4 * 4 + 1]);
        h.b = __floats2half2_rn(tile[s_local][c4 * 4 + 2], tile[s_local][c4 * 4 + 3]);
        *reinterpret_cast<H4*>(
            g_vol + ((size_t)b * SPAT + s0 + s_local) * CH + c0 + c4 * 4) = h;
    }
}

// ---------------------------------------------------------------------------
// Kernel 2: ROI-align rotated 3D gather.
// One warp per (roi, bin). Half-warps split the jz sample dimension;
// within a half-warp, lane owns 8 channels (one uint4 / 16B).
// Factored trilinear: m_xy = va*wz0 + vb*wz1 (z-lerp, invariant weights),
// then sum = Σ wxy * m_xy. 12 H-ops per half2 slot, fp32 cross-sample accum.
// Cross-half shfl reduce at end.
// ---------------------------------------------------------------------------
__device__ __forceinline__ __half2 h2(const unsigned int& u)
{
    return *reinterpret_cast<const __half2*>(&u);
}

__global__ void __launch_bounds__(256)
roi_gather_kernel(const float* __restrict__ rois,
                  const float* __restrict__ scale_p,
                  float* __restrict__ out,
                  int N)
{
    // 8 bins x 128 channels staging. float4 rows padded to 33 -> scalar reads
    // at pitch 132 floats are bank-conflict-free.
    __shared__ float4 s_out4[8][33];

    const int warp   = threadIdx.x >> 5;
    const int lane   = threadIdx.x & 31;
    const int zhalf  = lane >> 4;        // which jz sample this half-warp does
    const int laneIn = lane & 15;        // 8-channel group within half-warp
    const int bin    = blockIdx.x * 8 + warp;
    const int n      = blockIdx.y;

    float a[8] = {0.f, 0.f, 0.f, 0.f, 0.f, 0.f, 0.f, 0.f};

    if (bin < NBINS) {
        const float scale = *scale_p;
        const float* r = rois + (size_t)n * 8;
        const int   b  = (int)r[0];
        const float cx = r[1] * scale;
        const float cy = r[2] * scale;
        const float cz = r[3] * scale;
        const float sx = r[4] * scale;
        const float sy = r[5] * scale;
        const float sz = r[6] * scale;
        const float th = r[7];
        const float ct = cosf(th);
        const float st = sinf(th);

        // step = (size/nbins)/SR, matching reference arithmetic order
        const float stepx = (sx / 7.0f) * 0.5f;
        const float stepy = (sy / 7.0f) * 0.5f;
        const float stepz = (sz / 7.0f) * 0.5f;

        const int ow  = bin / 49;
        const int rem = bin % 49;
        const int ol  = rem / 7;
        const int oh  = rem % 7;

        // ---- z: loop-invariant for this lane (depends only on bin + zhalf)
        const int   iz = oh * 2 + zhalf;
        const float zs = (-sz * 0.5f + ((float)iz + 0.5f) * stepz) + cz;
        const float zval = ((zs > -1.0f) && (zs < (float)DH)) ? 1.0f : 0.0f;
        const float zc = fminf(fmaxf(zs, 0.f), (float)(DH - 1));
        const int   z0 = (int)floorf(zc);
        const float lz = zc - (float)z0;
        const float wz0 = (1.0f - lz) * zval;     // weight for z0 plane
        const float wz1 = lz * zval;              // weight for z1 plane
        const int   oz  = (z0 + 1 <= DH - 1) ? 256 : 0;

        // loop-invariant fp16 z-weights
        const __half2 wz0h = __float2half2_rn(wz0);
        const __half2 wz1h = __float2half2_rn(wz1);

        // byte-addressed base for this lane's 8-channel slice (16B per voxel,
        // 256B per spatial step). All corner offsets fit in 32-bit ints.
        const char* __restrict__ vbase =
            reinterpret_cast<const char*>(g_vol) + (size_t)b * SPAT * 256 + laneIn * 16;

        #pragma unroll
        for (int jx = 0; jx < 2; ++jx) {
            const int ix = ow * 2 + jx;
            const float fx = -sx * 0.5f + ((float)ix + 0.5f) * stepx;
            #pragma unroll
            for (int jy = 0; jy < 2; ++jy) {
                const int iy = ol * 2 + jy;
                const float fy = -sy * 0.5f + ((float)iy + 0.5f) * stepy;
                const float xs = ct * fx - st * fy + cx;
                const float ys = st * fx + ct * fy + cy;

                const bool vxy = (xs > -1.0f) && (xs < (float)DW) &&
                                 (ys > -1.0f) && (ys < (float)DL);
                if (!vxy) continue;

                const float xc = fminf(fmaxf(xs, 0.f), (float)(DW - 1));
                const float yc = fminf(fmaxf(ys, 0.f), (float)(DL - 1));
                const int x0 = (int)floorf(xc);
                const int y0 = (int)floorf(yc);
                const float lx = xc - (float)x0, hx = 1.f - lx;
                const float ly = yc - (float)y0, hy = 1.f - ly;

                const int ox = (x0 + 1 <= DW - 1) ? (DL * DH * 256) : 0;
                const int oy = (y0 + 1 <= DL - 1) ? (DH * 256)      : 0;
                const int o000 = ((x0 * DL + y0) * DH + z0) * 256;

                // 8 corner loads (2x2 xy corners x 2 z planes), batched for MLP
                const uint4 v00a = *reinterpret_cast<const uint4*>(vbase + o000);
                const uint4 v00b = *reinterpret_cast<const uint4*>(vbase + o000 + oz);
                const uint4 v01a = *reinterpret_cast<const uint4*>(vbase + o000 + oy);
                const uint4 v01b = *reinterpret_cast<const uint4*>(vbase + o000 + oy + oz);
                const uint4 v10a = *reinterpret_cast<const uint4*>(vbase + o000 + ox);
                const uint4 v10b = *reinterpret_cast<const uint4*>(vbase + o000 + ox + oz);
                const uint4 v11a = *reinterpret_cast<const uint4*>(vbase + o000 + ox + oy);
                const uint4 v11b = *reinterpret_cast<const uint4*>(vbase + o000 + ox + oy + oz);

                // fp16 duplicated xy weights (4 F2FP per iteration)
                const __half2 w00 = __float2half2_rn(hx * hy);
                const __half2 w01 = __float2half2_rn(hx * ly);
                const __half2 w10 = __float2half2_rn(lx * hy);
                const __half2 w11 = __float2half2_rn(lx * ly);

                const unsigned int* q00a = reinterpret_cast<const unsigned int*>(&v00a);
                const unsigned int* q00b = reinterpret_cast<const unsigned int*>(&v00b);
                const unsigned int* q01a = reinterpret_cast<const unsigned int*>(&v01a);
                const unsigned int* q01b = reinterpret_cast<const unsigned int*>(&v01b);
                const unsigned int* q10a = reinterpret_cast<const unsigned int*>(&v10a);
                const unsigned int* q10b = reinterpret_cast<const unsigned int*>(&v10b);
                const unsigned int* q11a = reinterpret_cast<const unsigned int*>(&v11a);
                const unsigned int* q11b = reinterpret_cast<const unsigned int*>(&v11b);

                #pragma unroll
                for (int k = 0; k < 4; ++k) {
                    // z-lerp per xy corner (independent, 2 ops each)
                    const __half2 m00 = __hfma2(h2(q00b[k]), wz1h, __hmul2(h2(q00a[k]), wz0h));
                    const __half2 m01 = __hfma2(h2(q01b[k]), wz1h, __hmul2(h2(q01a[k]), wz0h));
                    const __half2 m10 = __hfma2(h2(q10b[k]), wz1h, __hmul2(h2(q10a[k]), wz0h));
                    const __half2 m11 = __hfma2(h2(q11b[k]), wz1h, __hmul2(h2(q11a[k]), wz0h));
                    // xy combine
                    __half2 s = __hmul2(m00, w00);
                    s = __hfma2(m01, w01, s);
                    s = __hfma2(m10, w10, s);
                    s = __hfma2(m11, w11, s);
                    // widen once per slot per iteration
                    const float2 f = __half22float2(s);
                    a[k * 2 + 0] += f.x;
                    a[k * 2 + 1] += f.y;
                }
            }
        }
    }

    // Combine the two jz halves: lane L and L+16 hold the same channels.
    #pragma unroll
    for (int k = 0; k < 8; ++k) {
        a[k] += __shfl_xor_sync(0xffffffffu, a[k], 16);
        a[k] *= 0.125f;
    }

    // Stage: lanes 0..15 write 8 channels = 2 float4 (STS.128).
    if (zhalf == 0) {
        s_out4[warp][laneIn * 2 + 0] = make_float4(a[0], a[1], a[2], a[3]);
        s_out4[warp][laneIn * 2 + 1] = make_float4(a[4], a[5], a[6], a[7]);
    }
    __syncthreads();

    // Write: bins contiguous in gmem (out[n][c][bin]). Each group of 8 lanes
    // writes 8 consecutive bins for one channel -> full 32B sectors.
    {
        const float* s_outf = reinterpret_cast<const float*>(s_out4);
        const int bin_local = threadIdx.x & 7;
        const int bin_g     = blockIdx.x * 8 + bin_local;
        if (bin_g < NBINS) {
            const int cbase = threadIdx.x >> 3;   // 0..31
            #pragma unroll
            for (int k = 0; k < 4; ++k) {
                const int c = cbase + 32 * k;
                out[((size_t)n * CH + c) * NBINS + bin_g] =
                    s_outf[bin_local * 132 + c];
            }
        }
    }
}

extern "C" void kernel_launch(void* const* d_in, const int* in_sizes, int n_in,
                              void* d_out, int out_size)
{
    const float* input  = (const float*)d_in[0];
    const float* rois   = (const float*)d_in[1];
    const float* scale  = (const float*)d_in[2];
    float* out = (float*)d_out;
    const int N = in_sizes[1] / 8;

    {
        dim3 grid(SPAT / 32, CH / 32, BATCH);   // (8192, 4, 2)
        transpose_half_kernel<<<grid, 256>>>(input);
    }
    {
        dim3 grid((NBINS + 7) / 8, N);          // (43, 128)
        roi_gather_kernel<<<grid, 256>>>(rois, scale, out, N);
    }
}